// round 4
// baseline (speedup 1.0000x reference)
#include <cuda_runtime.h>
#include <math_constants.h>

// 5x5 per-channel max (cv2.dilate), SAME padding, (64,384,384,3) fp32.
// Fused dim L = W*C = 1152 floats = 288 float4. No smem, no barriers:
// horizontal 5-max (taps +-3,+-6 fused words) straight from global loads
// (neighbor vectors hit the same L1/L2 lines), vertical 5-max via a
// register ring over streamed rows. Thread t owns fused float4 column t.

#define B_    64
#define H_    384
#define L_    1152
#define L4_   288
#define TY    24              // output rows per block
#define NT    288             // threads = float4 columns per row

__device__ __forceinline__ float4 f4max(float4 a, float4 b) {
    return make_float4(fmaxf(a.x, b.x), fmaxf(a.y, b.y),
                       fmaxf(a.z, b.z), fmaxf(a.w, b.w));
}

__global__ __launch_bounds__(NT, 4)
void dilate5_kernel(const float* __restrict__ in,
                    const int* __restrict__ kptr,
                    float* __restrict__ out)
{
    const int k  = *kptr;
    const int t  = threadIdx.x;
    const int b  = blockIdx.y;
    const int y0 = blockIdx.x * TY;

    if (k == 5) {
        const float*  inb  = in  + (size_t)b * H_ * L_;
        float4*       outb = (float4*)out + (size_t)b * H_ * L4_;
        const float   NI   = -CUDART_INF_F;
        const float4  NEG4 = make_float4(NI, NI, NI, NI);
        const float2  NEG2 = make_float2(NI, NI);

        // x-edge predicates (per-thread constant)
        const bool hL2 = (t >= 2);        // float2 at word 4t-6
        const bool hL1 = (t >= 1);        // float4 at word 4t-4
        const bool hR1 = (t <= 286);      // float4 at word 4t+4
        const bool hR2 = (t <= 285);      // float2 at word 4t+8

        float4 ring[5];                    // hmax of rows (order-free: max over all)

        #pragma unroll
        for (int s = 0; s < TY + 4; ++s) {
            const int y = y0 - 2 + s;
            float4 h;
            if (y >= 0 && y < H_) {
                const float* rp = inb + (size_t)y * L_ + 4 * t;
                const float2 a0 = hL2 ? *(const float2*)(rp - 6) : NEG2;
                const float4 a1 = hL1 ? *(const float4*)(rp - 4) : NEG4;
                const float4 ow = *(const float4*)(rp);
                const float4 a3 = hR1 ? *(const float4*)(rp + 4) : NEG4;
                const float2 a4 = hR2 ? *(const float2*)(rp + 8) : NEG2;

                // h[j] = max over words {x-6, x-3, x, x+3, x+6}, x = 4t+j
                const float core = fmaxf(fmaxf(a1.y, ow.x), fmaxf(ow.w, a3.z));
                h.x = fmaxf(core, a0.x);
                h.w = fmaxf(core, a4.y);
                h.y = fmaxf(fmaxf(fmaxf(a0.y, a1.z), ow.y), fmaxf(a3.x, a3.w));
                h.z = fmaxf(fmaxf(fmaxf(a1.x, a1.w), ow.z), fmaxf(a3.y, a4.x));
            } else {
                h = NEG4;
            }
            ring[s % 5] = h;

            if (s >= 4) {
                const float4 o = f4max(f4max(f4max(ring[0], ring[1]),
                                             f4max(ring[2], ring[3])), ring[4]);
                outb[(size_t)(y0 + s - 4) * L4_ + t] = o;
            }
        }
    } else {
        // ---------------- generic fallback (any odd k), SAME padding ----------------
        const int padL = (k - 1) / 2;
        const int C = 3, W = 384;
        #pragma unroll
        for (int j = 0; j < 4; ++j) {
            const int x = 4 * t + j;
            const int w = x / C;
            const int c = x - w * C;
            for (int ty = 0; ty < TY; ++ty) {
                const int oy = y0 + ty;
                float m = -CUDART_INF_F;
                for (int ky = 0; ky < k; ky++) {
                    const int gy = oy - padL + ky;
                    if (gy < 0 || gy >= H_) continue;
                    for (int kx = 0; kx < k; kx++) {
                        const int gw = w - padL + kx;
                        if (gw < 0 || gw >= W) continue;
                        m = fmaxf(m, in[((size_t)b * H_ + gy) * L_ + gw * C + c]);
                    }
                }
                out[((size_t)b * H_ + oy) * L_ + x] = m;
            }
        }
    }
}

extern "C" void kernel_launch(void* const* d_in, const int* in_sizes, int n_in,
                              void* d_out, int out_size)
{
    const float* images = (const float*)d_in[0];
    const int*   kptr   = (const int*)d_in[1];
    float*       out    = (float*)d_out;

    dim3 grid(H_ / TY, B_);    // 16 x 64
    dim3 block(NT);            // 288
    dilate5_kernel<<<grid, block>>>(images, kptr, out);
}

// round 5
// speedup vs baseline: 1.1947x; 1.1947x over previous
#include <cuda_runtime.h>
#include <math_constants.h>

// 5x5 per-channel max (cv2.dilate), SAME padding, (64,384,384,3) fp32.
// Fused dim L = W*C = 1152 floats = 288 float4.
// Vertical 5-max: 1 aligned float4 LDG per row, 5-deep register ring (pure
// load stream, no barriers -> deep MLP). Horizontal 5-max (taps +-3,+-6 fused
// words) via 12 warp shuffles of the vertical-max vector from lanes l+-1,l+-2.
// Warp covers 32 f4 cols with 2 halo lanes per side: lane l -> col 28*w + l - 2,
// lanes 2..29 store outputs. 11 warps span the full fused row. No smem.

#define B_    64
#define H_    384
#define L_    1152
#define L4_   288
#define TY    24               // output rows per block
#define NW    11               // warps per block (11*28 = 308 >= 288)
#define NT    (NW * 32)        // 352 threads
#define FULL  0xffffffffu

__device__ __forceinline__ float4 f4max(float4 a, float4 b) {
    return make_float4(fmaxf(a.x, b.x), fmaxf(a.y, b.y),
                       fmaxf(a.z, b.z), fmaxf(a.w, b.w));
}

__global__ __launch_bounds__(NT, 3)
void dilate5_kernel(const float* __restrict__ in,
                    const int* __restrict__ kptr,
                    float* __restrict__ out)
{
    const int k  = *kptr;
    const int t  = threadIdx.x;
    const int w  = t >> 5;
    const int l  = t & 31;
    const int c  = 28 * w + l - 2;          // fused float4 column of this lane
    const int b  = blockIdx.y;
    const int y0 = blockIdx.x * TY;

    if (k == 5) {
        const bool ld_ok  = (c >= 0) && (c < L4_);
        const bool st_ok  = (l >= 2) && (l <= 29) && (c < L4_);

        const float4* inb  = (const float4*)in  + (size_t)b * H_ * L4_;
        float4*       outb = (float4*)      out + (size_t)b * H_ * L4_;
        const float   NI   = -CUDART_INF_F;
        const float4  NEG4 = make_float4(NI, NI, NI, NI);

        float4 ring[5];

        #pragma unroll
        for (int s = 0; s < TY + 4; ++s) {
            const int y = y0 - 2 + s;
            float4 v = NEG4;
            if (ld_ok && y >= 0 && y < H_)
                v = __ldg(&inb[(size_t)y * L4_ + c]);
            ring[s % 5] = v;

            if (s >= 4) {
                // vertical 5-max (order-free over ring)
                const float4 vm = f4max(f4max(f4max(ring[0], ring[1]),
                                              f4max(ring[2], ring[3])), ring[4]);

                // neighbor vm words via shuffles (halo lanes make edges valid)
                const float um1_x = __shfl_up_sync(FULL, vm.x, 1);
                const float um1_y = __shfl_up_sync(FULL, vm.y, 1);
                const float um1_z = __shfl_up_sync(FULL, vm.z, 1);
                const float um1_w = __shfl_up_sync(FULL, vm.w, 1);
                const float um2_z = __shfl_up_sync(FULL, vm.z, 2);
                const float um2_w = __shfl_up_sync(FULL, vm.w, 2);
                const float dm1_x = __shfl_down_sync(FULL, vm.x, 1);
                const float dm1_y = __shfl_down_sync(FULL, vm.y, 1);
                const float dm1_z = __shfl_down_sync(FULL, vm.z, 1);
                const float dm1_w = __shfl_down_sync(FULL, vm.w, 1);
                const float dm2_x = __shfl_down_sync(FULL, vm.x, 2);
                const float dm2_y = __shfl_down_sync(FULL, vm.y, 2);

                // horizontal 5-max; j0/j3 share a 4-tap core
                float4 o;
                const float core = fmaxf(fmaxf(um1_y, vm.x), fmaxf(vm.w, dm1_z));
                o.x = fmaxf(core, um2_z);
                o.w = fmaxf(core, dm2_y);
                o.y = fmaxf(fmaxf(fmaxf(um2_w, um1_z), vm.y), fmaxf(dm1_x, dm1_w));
                o.z = fmaxf(fmaxf(fmaxf(um1_x, um1_w), vm.z), fmaxf(dm1_y, dm2_x));

                if (st_ok)
                    outb[(size_t)(y0 + s - 4) * L4_ + c] = o;
            }
        }
    } else {
        // ---------------- generic fallback (any k), SAME padding ----------------
        const int padL = (k - 1) / 2;
        const int C = 3, W = 384;
        if (c >= 0 && c < L4_) {
            #pragma unroll
            for (int j = 0; j < 4; ++j) {
                const int x = 4 * c + j;
                const int ww = x / C;
                const int cc = x - ww * C;
                // avoid double-writes from halo duplication: only "owner" lanes
                if (!((l >= 2) && (l <= 29))) continue;
                for (int ty = 0; ty < TY; ++ty) {
                    const int oy = y0 + ty;
                    float m = -CUDART_INF_F;
                    for (int ky = 0; ky < k; ky++) {
                        const int gy = oy - padL + ky;
                        if (gy < 0 || gy >= H_) continue;
                        for (int kx = 0; kx < k; kx++) {
                            const int gw = ww - padL + kx;
                            if (gw < 0 || gw >= W) continue;
                            m = fmaxf(m, in[((size_t)b * H_ + gy) * L_ + gw * C + cc]);
                        }
                    }
                    out[((size_t)b * H_ + oy) * L_ + x] = m;
                }
            }
        }
    }
}

extern "C" void kernel_launch(void* const* d_in, const int* in_sizes, int n_in,
                              void* d_out, int out_size)
{
    const float* images = (const float*)d_in[0];
    const int*   kptr   = (const int*)d_in[1];
    float*       out    = (float*)d_out;

    dim3 grid(H_ / TY, B_);    // 16 x 64
    dim3 block(NT);            // 352
    dilate5_kernel<<<grid, block>>>(images, kptr, out);
}

// round 6
// speedup vs baseline: 1.2221x; 1.0230x over previous
#include <cuda_runtime.h>
#include <math_constants.h>

// 5x5 per-channel max (cv2.dilate), SAME padding, (64,384,384,3) fp32.
// Fused dim L = W*C = 1152 floats = 288 float4.
// Each thread owns 8 fused words (2 float4). Vertical 5-max via a 5-deep
// register ring over a pure LDG stream (no smem/barriers). Horizontal 5-max
// (taps +-3,+-6 fused words) needs only 6 neighbor words per side ->
// 12 shuffles per 8 outputs. Stride-3 pair trick: m3[j]=max(w,w+3),
// H[j]=max(m3[j-6],m3[j],w[j+6]).
// Warp: lane l owns 8-word block o=30*w+l-1; lanes 1..30 store, 0/31 halo.
// 5 warps cover a full fused row (150 blocks >= 144).

#define B_    64
#define H_    384
#define L_    1152
#define L4_   288
#define NB8   144              // 8-word blocks per row
#define TY    24               // output rows per block
#define NW    5
#define NT    (NW * 32)        // 160 threads
#define FULL  0xffffffffu

__device__ __forceinline__ float4 f4max(float4 a, float4 b) {
    return make_float4(fmaxf(a.x, b.x), fmaxf(a.y, b.y),
                       fmaxf(a.z, b.z), fmaxf(a.w, b.w));
}

__global__ __launch_bounds__(NT, 4)
void dilate5_kernel(const float* __restrict__ in,
                    const int* __restrict__ kptr,
                    float* __restrict__ out)
{
    const int k  = *kptr;
    const int t  = threadIdx.x;
    const int w  = t >> 5;
    const int l  = t & 31;
    const int o  = 30 * w + l - 1;       // 8-word block index (-1 .. 150)
    const int c0 = 2 * o;                // first float4 col
    const int c1 = 2 * o + 1;
    const int b  = blockIdx.y;
    const int y0 = blockIdx.x * TY;

    if (k == 5) {
        const bool ok0 = (o >= 0) && (c0 < L4_);
        const bool ok1 = (o >= 0) && (c1 < L4_);
        const bool st_ok = (l >= 1) && (l <= 30) && (o >= 0) && (o < NB8);

        const float4* inb  = (const float4*)in  + (size_t)b * H_ * L4_;
        float4*       outb = (float4*)      out + (size_t)b * H_ * L4_;
        const float   NI   = -CUDART_INF_F;
        const float4  NEG4 = make_float4(NI, NI, NI, NI);

        float4 ringA[5], ringB[5];

        #pragma unroll
        for (int s = 0; s < TY + 4; ++s) {
            const int y = y0 - 2 + s;
            const bool yok = (y >= 0) && (y < H_);
            float4 vA = NEG4, vB = NEG4;
            if (ok0 && yok) vA = __ldg(&inb[(size_t)y * L4_ + c0]);
            if (ok1 && yok) vB = __ldg(&inb[(size_t)y * L4_ + c1]);
            ringA[s % 5] = vA;
            ringB[s % 5] = vB;

            if (s >= 4) {
                // vertical 5-max (order-free over ring)
                const float4 mA = f4max(f4max(f4max(ringA[0], ringA[1]),
                                              f4max(ringA[2], ringA[3])), ringA[4]);
                const float4 mB = f4max(f4max(f4max(ringB[0], ringB[1]),
                                              f4max(ringB[2], ringB[3])), ringB[4]);
                // own words v0..v7
                const float v0 = mA.x, v1 = mA.y, v2 = mA.z, v3 = mA.w;
                const float v4 = mB.x, v5 = mB.y, v6 = mB.z, v7 = mB.w;

                // left neighbor words -6..-1 = left lane's v2..v7
                const float l0 = __shfl_up_sync(FULL, v2, 1);
                const float l1 = __shfl_up_sync(FULL, v3, 1);
                const float l2 = __shfl_up_sync(FULL, v4, 1);
                const float l3 = __shfl_up_sync(FULL, v5, 1);
                const float l4 = __shfl_up_sync(FULL, v6, 1);
                const float l5 = __shfl_up_sync(FULL, v7, 1);
                // right neighbor words 8..13 = right lane's v0..v5
                const float r0 = __shfl_down_sync(FULL, v0, 1);
                const float r1 = __shfl_down_sync(FULL, v1, 1);
                const float r2 = __shfl_down_sync(FULL, v2, 1);
                const float r3 = __shfl_down_sync(FULL, v3, 1);
                const float r4 = __shfl_down_sync(FULL, v4, 1);
                const float r5 = __shfl_down_sync(FULL, v5, 1);

                // m3[j] = max(w[j], w[j+3])
                const float m3_m6 = fmaxf(l0, l3);
                const float m3_m5 = fmaxf(l1, l4);
                const float m3_m4 = fmaxf(l2, l5);
                const float m3_m3 = fmaxf(l3, v0);
                const float m3_m2 = fmaxf(l4, v1);
                const float m3_m1 = fmaxf(l5, v2);
                const float m3_0  = fmaxf(v0, v3);
                const float m3_1  = fmaxf(v1, v4);
                const float m3_2  = fmaxf(v2, v5);
                const float m3_3  = fmaxf(v3, v6);
                const float m3_4  = fmaxf(v4, v7);
                const float m3_5  = fmaxf(v5, r0);
                const float m3_6  = fmaxf(v6, r1);
                const float m3_7  = fmaxf(v7, r2);

                // H[j] = max(m3[j-6], m3[j], w[j+6])
                float4 oA, oB;
                oA.x = fmaxf(m3_m6, fmaxf(m3_0, v6));
                oA.y = fmaxf(m3_m5, fmaxf(m3_1, v7));
                oA.z = fmaxf(m3_m4, fmaxf(m3_2, r0));
                oA.w = fmaxf(m3_m3, fmaxf(m3_3, r1));
                oB.x = fmaxf(m3_m2, fmaxf(m3_4, r2));
                oB.y = fmaxf(m3_m1, fmaxf(m3_5, r3));
                oB.z = fmaxf(m3_0,  fmaxf(m3_6, r4));
                oB.w = fmaxf(m3_1,  fmaxf(m3_7, r5));

                if (st_ok) {
                    const size_t rowo = (size_t)(y0 + s - 4) * L4_;
                    outb[rowo + c0] = oA;
                    outb[rowo + c1] = oB;
                }
            }
        }
    } else {
        // ---------------- generic fallback (any k), SAME padding ----------------
        const int padL = (k - 1) / 2;
        const int C = 3, W = 384;
        if ((l >= 1) && (l <= 30) && o >= 0 && o < NB8) {
            for (int j = 0; j < 8; ++j) {
                const int x = 8 * o + j;          // fused col (word)
                const int ww = x / C;
                const int cc = x - ww * C;
                for (int ty = 0; ty < TY; ++ty) {
                    const int oy = y0 + ty;
                    float m = -CUDART_INF_F;
                    for (int ky = 0; ky < k; ky++) {
                        const int gy = oy - padL + ky;
                        if (gy < 0 || gy >= H_) continue;
                        for (int kx = 0; kx < k; kx++) {
                            const int gw = ww - padL + kx;
                            if (gw < 0 || gw >= W) continue;
                            m = fmaxf(m, in[((size_t)b * H_ + gy) * L_ + gw * C + cc]);
                        }
                    }
                    out[((size_t)b * H_ + oy) * L_ + x] = m;
                }
            }
        }
    }
}

extern "C" void kernel_launch(void* const* d_in, const int* in_sizes, int n_in,
                              void* d_out, int out_size)
{
    const float* images = (const float*)d_in[0];
    const int*   kptr   = (const int*)d_in[1];
    float*       out    = (float*)d_out;

    dim3 grid(H_ / TY, B_);    // 16 x 64
    dim3 block(NT);            // 160
    dilate5_kernel<<<grid, block>>>(images, kptr, out);
}